// round 13
// baseline (speedup 1.0000x reference)
#include <cuda_runtime.h>
#include <cuda_bf16.h>
#include <cstdint>
#include <math.h>

#define D    128
#define E    16384
#define NN   10000
#define LDP  132
#define SLICE_FLOATS (D * D)          // 16384 floats = 64 KB
#define SLICE_BYTES  (D * D * 4)

// ---------------- device scratch (static, allocation-free) ----------------
__device__ float g_HT [D * E];                 // h transposed: [k][e]
__device__ float g_XJ [E * D];                 // gathered x[src]
__device__ float g_W2T[(D + 1) * D * D];       // [k][o][swz(i)], rna-tf32; k=128 is b2
__device__ float g_SEG[NN * D];                // scatter sum
__device__ float g_CNT[NN];                    // per-node counts
__device__ int   g_IDXW;                       // 1 if edge_index is int64, 0 if int32

// ---------------- helpers ----------------
__device__ __forceinline__ unsigned rna_tf32(float x) {
    unsigned u; asm("cvt.rna.tf32.f32 %0, %1;" : "=r"(u) : "f"(x)); return u;
}
__device__ __forceinline__ float rna_tf32_f(float x) { return __uint_as_float(rna_tf32(x)); }
__device__ __forceinline__ uint32_t s2u(const void* p) {
    return (uint32_t)__cvta_generic_to_shared(p);
}
__device__ __forceinline__ void mbar_init(uint32_t m, uint32_t cnt) {
    asm volatile("mbarrier.init.shared.b64 [%0], %1;" :: "r"(m), "r"(cnt) : "memory");
}
__device__ __forceinline__ void mbar_arrive_tx(uint32_t m, uint32_t tx) {
    asm volatile("mbarrier.arrive.expect_tx.shared.b64 _, [%0], %1;" :: "r"(m), "r"(tx) : "memory");
}
__device__ __forceinline__ void bulk_g2s(uint32_t sdst, const void* gsrc, uint32_t bytes, uint32_t m) {
    asm volatile("cp.async.bulk.shared::cta.global.mbarrier::complete_tx::bytes [%0], [%1], %2, [%3];"
                 :: "r"(sdst), "l"(gsrc), "r"(bytes), "r"(m) : "memory");
}
__device__ __forceinline__ void mbar_wait(uint32_t m, uint32_t parity) {
    asm volatile(
        "{\n\t.reg .pred P;\n"
        "W_%=:\n\t"
        "mbarrier.try_wait.parity.acquire.cta.shared::cta.b64 P, [%0], %1, 0x989680;\n\t"
        "@P bra D_%=;\n\t"
        "bra W_%=;\n"
        "D_%=:\n\t}"
        :: "r"(m), "r"(parity) : "memory");
}
// index loads, dtype-robust (g_IDXW set by k_detect)
__device__ __forceinline__ int ld_src(const void* ei, int wide, int e) {
    return wide ? (int)((const long long*)ei)[e] : ((const int*)ei)[e];
}
__device__ __forceinline__ int ld_dst(const void* ei, int wide, int e) {
    return wide ? (int)((const long long*)ei)[E + e] : ((const int*)ei)[E + e];
}

// ---------------- 0. dtype detect (reads only bytes [0, E*8) — in-bounds either way) ----------------
__global__ void k_detect(const void* ei) {
    int e = blockIdx.x * 256 + threadIdx.x;
    if (e >= E) return;
    long long v = ((const long long*)ei)[e];
    if (v < 0 || v >= (long long)NN) {
        if (g_IDXW) atomicExch(&g_IDXW, 0);
    }
}

// ---------------- 1. zero accumulators, arm flag ----------------
__global__ void k_zero() {
    int i = blockIdx.x * 256 + threadIdx.x;
    if (i == 0) g_IDXW = 1;
    if (i < NN * D)           g_SEG[i] = 0.0f;
    else if (i < NN * D + NN) g_CNT[i - NN * D] = 0.0f;
}

// ---------------- 2. transpose+swizzle w2 -> W2T[k][o][swz(i)] ----------------
// grid (129, 16) block (32, 8). blockIdx.x = k (128 == b2 slice).
__global__ void k_w2t(const float* __restrict__ w2, const float* __restrict__ b2) {
    __shared__ float tile[32][33];
    int k  = blockIdx.x;
    int ti = blockIdx.y & 3, to = blockIdx.y >> 2;
    int tx = threadIdx.x, ty = threadIdx.y;
    const float* src = (k < D) ? (w2 + (size_t)k * D * D) : b2;  // indexed [i*D + o]
#pragma unroll
    for (int j = 0; j < 4; j++) {
        int i = ti * 32 + ty + j * 8;
        int o = to * 32 + tx;
        tile[ty + j * 8][tx] = rna_tf32_f(src[(size_t)i * D + o]);   // coalesced in o
    }
    __syncthreads();
    float* dst = g_W2T + (size_t)k * SLICE_FLOATS;
#pragma unroll
    for (int j = 0; j < 4; j++) {
        int o = to * 32 + ty + j * 8;
        int i = ti * 32 + tx;
        int sw = ((((i >> 2) ^ (o & 7)) << 2) | (i & 3));
        dst[o * D + sw] = tile[tx][ty + j * 8];                      // swizzle stays in 128B line
    }
}

// ---------------- 3. h = relu(EA @ w1 + b1), stored transposed g_HT[k][e] ----------------
__global__ void __launch_bounds__(256) k_h(const float* __restrict__ ea,
                                           const float* __restrict__ w1,
                                           const float* __restrict__ b1) {
    extern __shared__ float sm[];
    float* sEA = sm;             // [128][LDP]
    float* sW1 = sm + D * LDP;   // [128][LDP]  (w1[i][c])
    int t = threadIdx.x;
    int e0 = blockIdx.x * 128;
    for (int idx = t; idx < D * 32; idx += 256) {
        int r = idx >> 5, c4 = idx & 31;
        *(float4*)&sEA[r * LDP + c4 * 4] = *(const float4*)&ea[(size_t)(e0 + r) * D + c4 * 4];
        *(float4*)&sW1[r * LDP + c4 * 4] = *(const float4*)&w1[(size_t)r * D + c4 * 4];
    }
    __syncthreads();
    int tx = t & 15, ty = t >> 4;
    int r0 = ty * 8, c0 = tx * 8;
    float acc[8][8];
#pragma unroll
    for (int u = 0; u < 8; u++)
#pragma unroll
        for (int v = 0; v < 8; v++) acc[u][v] = 0.0f;
    for (int i = 0; i < D; i++) {
        float ar[8];
#pragma unroll
        for (int u = 0; u < 8; u++) ar[u] = sEA[(r0 + u) * LDP + i];
        float4 bA = *(float4*)&sW1[i * LDP + c0];
        float4 bB = *(float4*)&sW1[i * LDP + c0 + 4];
        float br[8] = {bA.x, bA.y, bA.z, bA.w, bB.x, bB.y, bB.z, bB.w};
#pragma unroll
        for (int u = 0; u < 8; u++)
#pragma unroll
            for (int v = 0; v < 8; v++) acc[u][v] = fmaf(ar[u], br[v], acc[u][v]);
    }
#pragma unroll
    for (int u = 0; u < 8; u++)
#pragma unroll
        for (int v = 0; v < 8; v++) {
            float h = fmaxf(acc[u][v] + b1[c0 + v], 0.0f);
            g_HT[(size_t)(c0 + v) * E + (e0 + r0 + u)] = h;
        }
}

// ---------------- 4. gather XJ = x[src]; edge counts ----------------
__global__ void k_gather(const float* __restrict__ x, const void* __restrict__ ei) {
    int idx = blockIdx.x * 256 + threadIdx.x;
    if (idx >= E * 32) return;
    int wide = g_IDXW;
    int e = idx >> 5, c = idx & 31;
    int s = ld_src(ei, wide, e);
    ((float4*)g_XJ)[(size_t)e * 32 + c] = *(const float4*)&x[(size_t)s * D + c * 4];
}
__global__ void k_cnt(const void* __restrict__ ei) {
    int e = blockIdx.x * 256 + threadIdx.x;
    if (e < E) atomicAdd(&g_CNT[ld_dst(ei, g_IDXW, e)], 1.0f);
}

// ---------------- 5. main bilinear: per-edge tile, 129 tf32 GEMM slices ----------------
// grid 128 CTAs (128 edges each), 256 threads = 8 warps in 4(m) x 2(n) grid.
__global__ void __launch_bounds__(256, 1) k_main(const void* __restrict__ ei) {
    extern __shared__ float sm[];
    float* sXJ  = sm;                    // [128][LDP]        16896 floats
    float* sB   = sm + 16896;            // 2 x 16384 floats (swizzled slices)
    float* sHc  = sm + 49664;            // 2 x 128
    int*   sDST = (int*)(sm + 49920);    // 128
    uint32_t mb0 = s2u(sm) + 50048 * 4;  // 2 mbarriers (8B each)
    uint32_t mb1 = mb0 + 8;

    int t = threadIdx.x, lane = t & 31, w = t >> 5;
    int wm = w & 3, wn = w >> 2;
    int lm = lane >> 2, lw = lane & 3;
    int e0 = blockIdx.x * 128;

    if (t == 0) { mbar_init(mb0, 1); mbar_init(mb1, 1); }
    __syncthreads();

    if (t == 0) {  // issue slice 0
        mbar_arrive_tx(mb0, SLICE_BYTES);
        bulk_g2s(s2u(sB), g_W2T, SLICE_BYTES, mb0);
    }
    if (t < 128) {
        sHc[t]  = g_HT[e0 + t];          // h column k=0
        sDST[t] = ld_dst(ei, g_IDXW, e0 + t);
    }
    for (int idx = t; idx < D * 32; idx += 256) {
        int r = idx >> 5, c4 = idx & 31;
        *(float4*)&sXJ[r * LDP + c4 * 4] = *(const float4*)&g_XJ[(size_t)(e0 + r) * D + c4 * 4];
    }
    __syncthreads();

    float acc[2][8][4];
#pragma unroll
    for (int m = 0; m < 2; m++)
#pragma unroll
        for (int n = 0; n < 8; n++)
#pragma unroll
            for (int q = 0; q < 4; q++) acc[m][n][q] = 0.0f;

    int abase[2];
#pragma unroll
    for (int m = 0; m < 2; m++) abase[m] = (wm * 32 + m * 16 + lm) * LDP + lw;
    int bo[8];
#pragma unroll
    for (int n = 0; n < 8; n++) bo[n] = (wn * 64 + n * 8 + lm) * D + lw;

#pragma unroll 1
    for (int k = 0; k <= D; k++) {
        int b = k & 1;
        if (k < D) {  // prefetch slice k+1 into the other buffer (freed by last iter's syncthreads)
            if (t == 0) {
                uint32_t mb = (b ^ 1) ? mb1 : mb0;
                mbar_arrive_tx(mb, SLICE_BYTES);
                bulk_g2s(s2u(sB) + (uint32_t)(b ^ 1) * SLICE_BYTES,
                         g_W2T + (size_t)(k + 1) * SLICE_FLOATS, SLICE_BYTES, mb);
            }
            if (t < 128)
                sHc[(b ^ 1) * 128 + t] = (k + 1 < D) ? g_HT[(size_t)(k + 1) * E + e0 + t] : 1.0f;
        }
        mbar_wait(b ? mb1 : mb0, (uint32_t)((k >> 1) & 1));

        const float* B = sB + b * SLICE_FLOATS;
        float s[4];
#pragma unroll
        for (int j = 0; j < 4; j++) s[j] = sHc[b * 128 + wm * 32 + j * 8 + lm];

#pragma unroll 4
        for (int is = 0; is < 16; is++) {
            int i8 = is * 8;
            unsigned a[2][4];
#pragma unroll
            for (int m = 0; m < 2; m++) {
                int ba = abase[m] + i8;
                a[m][0] = rna_tf32(sXJ[ba]               * s[2 * m]);
                a[m][1] = rna_tf32(sXJ[ba + 8 * LDP]     * s[2 * m + 1]);
                a[m][2] = rna_tf32(sXJ[ba + 4]           * s[2 * m]);
                a[m][3] = rna_tf32(sXJ[ba + 8 * LDP + 4] * s[2 * m + 1]);
            }
            int sw0 = (((is * 2)     ^ lm) << 2);
            int sw1 = (((is * 2 + 1) ^ lm) << 2);
#pragma unroll
            for (int n = 0; n < 8; n++) {
                unsigned f0 = __float_as_uint(B[bo[n] + sw0]);
                unsigned f1 = __float_as_uint(B[bo[n] + sw1]);
#pragma unroll
                for (int m = 0; m < 2; m++) {
                    asm volatile(
                        "mma.sync.aligned.m16n8k8.row.col.f32.tf32.tf32.f32 "
                        "{%0,%1,%2,%3}, {%4,%5,%6,%7}, {%8,%9}, {%0,%1,%2,%3};"
                        : "+f"(acc[m][n][0]), "+f"(acc[m][n][1]),
                          "+f"(acc[m][n][2]), "+f"(acc[m][n][3])
                        : "r"(a[m][0]), "r"(a[m][1]), "r"(a[m][2]), "r"(a[m][3]),
                          "r"(f0), "r"(f1));
                }
            }
        }
        __syncthreads();  // all done reading buffer b + sHc slot before re-fill next iter
    }

    // scatter-add into g_SEG
#pragma unroll
    for (int m = 0; m < 2; m++) {
        int rl = wm * 32 + m * 16 + lm;
        int dl = sDST[rl], dh = sDST[rl + 8];
#pragma unroll
        for (int n = 0; n < 8; n++) {
            int c = wn * 64 + n * 8 + lw * 2;
            atomicAdd(&g_SEG[(size_t)dl * D + c],     acc[m][n][0]);
            atomicAdd(&g_SEG[(size_t)dl * D + c + 1], acc[m][n][1]);
            atomicAdd(&g_SEG[(size_t)dh * D + c],     acc[m][n][2]);
            atomicAdd(&g_SEG[(size_t)dh * D + c + 1], acc[m][n][3]);
        }
    }
}

// ---------------- 6. out = x + gelu(seg/cnt + x@root + bias) ----------------
__global__ void __launch_bounds__(256) k_out(const float* __restrict__ x,
                                             const float* __restrict__ root,
                                             const float* __restrict__ bias,
                                             float* __restrict__ out) {
    extern __shared__ float sm[];
    float* sX = sm;              // [128][LDP]
    float* sR = sm + D * LDP;    // [128][LDP]  root[i][c]
    int t = threadIdx.x;
    int v0 = blockIdx.x * 128;
    for (int idx = t; idx < D * 32; idx += 256) {
        int r = idx >> 5, c4 = idx & 31;
        float4 z = make_float4(0.f, 0.f, 0.f, 0.f);
        *(float4*)&sX[r * LDP + c4 * 4] =
            (v0 + r < NN) ? *(const float4*)&x[(size_t)(v0 + r) * D + c4 * 4] : z;
        *(float4*)&sR[r * LDP + c4 * 4] = *(const float4*)&root[(size_t)r * D + c4 * 4];
    }
    __syncthreads();
    int tx = t & 15, ty = t >> 4;
    int r0 = ty * 8, c0 = tx * 8;
    float acc[8][8];
#pragma unroll
    for (int u = 0; u < 8; u++)
#pragma unroll
        for (int v = 0; v < 8; v++) acc[u][v] = 0.0f;
    for (int i = 0; i < D; i++) {
        float ar[8];
#pragma unroll
        for (int u = 0; u < 8; u++) ar[u] = sX[(r0 + u) * LDP + i];
        float4 bA = *(float4*)&sR[i * LDP + c0];
        float4 bB = *(float4*)&sR[i * LDP + c0 + 4];
        float br[8] = {bA.x, bA.y, bA.z, bA.w, bB.x, bB.y, bB.z, bB.w};
#pragma unroll
        for (int u = 0; u < 8; u++)
#pragma unroll
            for (int v = 0; v < 8; v++) acc[u][v] = fmaf(ar[u], br[v], acc[u][v]);
    }
#pragma unroll
    for (int u = 0; u < 8; u++) {
        int vtx = v0 + r0 + u;
        if (vtx >= NN) continue;
        float inv = 1.0f / fmaxf(g_CNT[vtx], 1.0f);
#pragma unroll
        for (int v = 0; v < 8; v++) {
            int c = c0 + v;
            float conv = acc[u][v] + g_SEG[(size_t)vtx * D + c] * inv + bias[c];
            float g = 0.5f * conv * (1.0f + erff(conv * 0.70710678118654752f));
            out[(size_t)vtx * D + c] = x[(size_t)vtx * D + c] + g;
        }
    }
}

// ---------------- host ----------------
#define SMEM_GEMM (2 * D * LDP * 4)                 // 135168
#define SMEM_MAIN (50048 * 4 + 16)                  // 200208

extern "C" void kernel_launch(void* const* d_in, const int* in_sizes, int n_in,
                              void* d_out, int out_size) {
    const float* x    = (const float*)d_in[0];
    const void*  ei   = d_in[1];                    // int32 or int64 — detected on device
    const float* ea   = (const float*)d_in[2];
    const float* w1   = (const float*)d_in[3];
    const float* b1   = (const float*)d_in[4];
    const float* w2   = (const float*)d_in[5];
    const float* b2   = (const float*)d_in[6];
    const float* root = (const float*)d_in[7];
    const float* bias = (const float*)d_in[8];
    float* out = (float*)d_out;

    cudaFuncSetAttribute(k_h,    cudaFuncAttributeMaxDynamicSharedMemorySize, SMEM_GEMM);
    cudaFuncSetAttribute(k_out,  cudaFuncAttributeMaxDynamicSharedMemorySize, SMEM_GEMM);
    cudaFuncSetAttribute(k_main, cudaFuncAttributeMaxDynamicSharedMemorySize, SMEM_MAIN);

    k_zero  <<<(NN * D + NN + 255) / 256, 256>>>();
    k_detect<<<E / 256, 256>>>(ei);
    k_w2t   <<<dim3(129, 16), dim3(32, 8)>>>(w2, b2);
    k_h     <<<E / 128, 256, SMEM_GEMM>>>(ea, w1, b1);
    k_gather<<<(E * 32) / 256, 256>>>(x, ei);
    k_cnt   <<<E / 256, 256>>>(ei);
    k_main  <<<E / 128, 256, SMEM_MAIN>>>(ei);
    k_out   <<<(NN + 127) / 128, 256, SMEM_GEMM>>>(x, root, bias, out);
}

// round 15
// speedup vs baseline: 1.0609x; 1.0609x over previous
#include <cuda_runtime.h>
#include <cuda_bf16.h>
#include <cstdint>
#include <math.h>

#define D    128
#define E    16384
#define NN   10000
#define LDP  132
#define HS_FLOATS 8192                // half-slice: 64 i x 128 o = 32 KB
#define HS_BYTES  (HS_FLOATS * 4)
#define NSLICE    258                 // 2 halves x 129 (k=128 is b2)

// ---------------- device scratch (static, allocation-free) ----------------
__device__ float g_HT [D * E];                             // h transposed: [k][e]
__device__ float g_XJ [E * D];                             // gathered x[src]
__device__ __align__(1024) float g_W2T[NSLICE * HS_FLOATS];// [half][k][o][swz(i_loc)] rna-tf32
__device__ float g_SEG[NN * D];                            // scatter sum
__device__ float g_CNT[NN];                                // per-node counts
__device__ int   g_IDXW;                                   // 1 if edge_index int64, 0 if int32

// ---------------- helpers ----------------
__device__ __forceinline__ unsigned rna_tf32(float x) {
    unsigned u; asm("cvt.rna.tf32.f32 %0, %1;" : "=r"(u) : "f"(x)); return u;
}
__device__ __forceinline__ float rna_tf32_f(float x) { return __uint_as_float(rna_tf32(x)); }
__device__ __forceinline__ uint32_t s2u(const void* p) {
    return (uint32_t)__cvta_generic_to_shared(p);
}
__device__ __forceinline__ void mbar_init(uint32_t m, uint32_t cnt) {
    asm volatile("mbarrier.init.shared.b64 [%0], %1;" :: "r"(m), "r"(cnt) : "memory");
}
__device__ __forceinline__ void mbar_arrive_tx(uint32_t m, uint32_t tx) {
    asm volatile("mbarrier.arrive.expect_tx.shared.b64 _, [%0], %1;" :: "r"(m), "r"(tx) : "memory");
}
__device__ __forceinline__ void bulk_g2s(uint32_t sdst, const void* gsrc, uint32_t bytes, uint32_t m) {
    asm volatile("cp.async.bulk.shared::cta.global.mbarrier::complete_tx::bytes [%0], [%1], %2, [%3];"
                 :: "r"(sdst), "l"(gsrc), "r"(bytes), "r"(m) : "memory");
}
__device__ __forceinline__ void mbar_wait(uint32_t m, uint32_t parity) {
    asm volatile(
        "{\n\t.reg .pred P;\n"
        "W_%=:\n\t"
        "mbarrier.try_wait.parity.acquire.cta.shared::cta.b64 P, [%0], %1, 0x989680;\n\t"
        "@P bra D_%=;\n\t"
        "bra W_%=;\n"
        "D_%=:\n\t}"
        :: "r"(m), "r"(parity) : "memory");
}
__device__ __forceinline__ int ld_src(const void* ei, int wide, int e) {
    return wide ? (int)((const long long*)ei)[e] : ((const int*)ei)[e];
}
__device__ __forceinline__ int ld_dst(const void* ei, int wide, int e) {
    return wide ? (int)((const long long*)ei)[E + e] : ((const int*)ei)[E + e];
}

// ---------------- 0. dtype detect ----------------
__global__ void k_detect(const void* ei) {
    int e = blockIdx.x * 256 + threadIdx.x;
    if (e >= E) return;
    long long v = ((const long long*)ei)[e];
    if (v < 0 || v >= (long long)NN) {
        if (g_IDXW) atomicExch(&g_IDXW, 0);
    }
}

// ---------------- 1. zero accumulators, arm flag ----------------
__global__ void k_zero() {
    int i = blockIdx.x * 256 + threadIdx.x;
    if (i == 0) g_IDXW = 1;
    if (i < NN * D)           g_SEG[i] = 0.0f;
    else if (i < NN * D + NN) g_CNT[i - NN * D] = 0.0f;
}

// ---------------- 2. w2 -> W2T half-slices [half][k][o][swz(i_loc)] ----------------
// grid (129, 16), block (32, 8). blockIdx.x = k (128 == b2 slice).
__global__ void k_w2t(const float* __restrict__ w2, const float* __restrict__ b2) {
    __shared__ float tile[32][33];
    int k  = blockIdx.x;                               // 0..128
    int ti = blockIdx.y & 3, to = blockIdx.y >> 2;
    int tx = threadIdx.x, ty = threadIdx.y;
    const float* src = (k < D) ? (w2 + (size_t)k * D * D) : b2;   // [i*D + o], b2 is D*D
#pragma unroll
    for (int j = 0; j < 4; j++) {
        int i = ti * 32 + ty + j * 8;
        int o = to * 32 + tx;
        tile[ty + j * 8][tx] = rna_tf32_f(src[(size_t)i * D + o]);  // coalesced in o
    }
    __syncthreads();
#pragma unroll
    for (int j = 0; j < 4; j++) {
        int o = to * 32 + ty + j * 8;
        int i = ti * 32 + tx;
        int half = i >> 6, il = i & 63, g = il >> 2;
        size_t fidx = (size_t)(half * 129 + k) * HS_FLOATS
                    + o * 64 + ((g ^ (o & 7)) << 2) + (il & 3);
        g_W2T[fidx] = tile[tx][ty + j * 8];             // 128B/warp store region
    }
}

// ---------------- 3. h = relu(EA @ w1 + b1) -> g_HT[k][e] ----------------
__global__ void __launch_bounds__(256) k_h(const float* __restrict__ ea,
                                           const float* __restrict__ w1,
                                           const float* __restrict__ b1) {
    extern __shared__ float sm[];
    float* sEA = sm;
    float* sW1 = sm + D * LDP;
    int t = threadIdx.x;
    int e0 = blockIdx.x * 128;
    for (int idx = t; idx < D * 32; idx += 256) {
        int r = idx >> 5, c4 = idx & 31;
        *(float4*)&sEA[r * LDP + c4 * 4] = *(const float4*)&ea[(size_t)(e0 + r) * D + c4 * 4];
        *(float4*)&sW1[r * LDP + c4 * 4] = *(const float4*)&w1[(size_t)r * D + c4 * 4];
    }
    __syncthreads();
    int tx = t & 15, ty = t >> 4;
    int r0 = ty * 8, c0 = tx * 8;
    float acc[8][8];
#pragma unroll
    for (int u = 0; u < 8; u++)
#pragma unroll
        for (int v = 0; v < 8; v++) acc[u][v] = 0.0f;
    for (int i = 0; i < D; i++) {
        float ar[8];
#pragma unroll
        for (int u = 0; u < 8; u++) ar[u] = sEA[(r0 + u) * LDP + i];
        float4 bA = *(float4*)&sW1[i * LDP + c0];
        float4 bB = *(float4*)&sW1[i * LDP + c0 + 4];
        float br[8] = {bA.x, bA.y, bA.z, bA.w, bB.x, bB.y, bB.z, bB.w};
#pragma unroll
        for (int u = 0; u < 8; u++)
#pragma unroll
            for (int v = 0; v < 8; v++) acc[u][v] = fmaf(ar[u], br[v], acc[u][v]);
    }
#pragma unroll
    for (int u = 0; u < 8; u++)
#pragma unroll
        for (int v = 0; v < 8; v++) {
            float h = fmaxf(acc[u][v] + b1[c0 + v], 0.0f);
            g_HT[(size_t)(c0 + v) * E + (e0 + r0 + u)] = h;
        }
}

// ---------------- 4. gather XJ = x[src]; edge counts ----------------
__global__ void k_gather(const float* __restrict__ x, const void* __restrict__ ei) {
    int idx = blockIdx.x * 256 + threadIdx.x;
    if (idx >= E * 32) return;
    int wide = g_IDXW;
    int e = idx >> 5, c = idx & 31;
    int s = ld_src(ei, wide, e);
    ((float4*)g_XJ)[(size_t)e * 32 + c] = *(const float4*)&x[(size_t)s * D + c * 4];
}
__global__ void k_cnt(const void* __restrict__ ei) {
    int e = blockIdx.x * 256 + threadIdx.x;
    if (e < E) atomicAdd(&g_CNT[ld_dst(ei, g_IDXW, e)], 1.0f);
}

// ---------------- 5. main bilinear: const-A two-pass, h in epilogue ----------------
// 128 CTAs x 256 threads (8 warps, 4m x 2n; warp tile 32e x 64o).
// For half in {0,1}: A = rna(XJ[:, half*64:+64]) resident in registers.
//   For k in 0..128: P = A @ W2half[k]; final += h_k (.) P.   (k=128: W=b2, h=1)
__global__ void __launch_bounds__(256, 1) k_main(const void* __restrict__ ei) {
    extern __shared__ float sm[];
    float* sB  = sm;                         // 3 x 8192 floats (96 KB ring)
    float* sXJ = sm + 3 * HS_FLOATS;         // [128][LDP]
    uint32_t mbb = s2u(sm + 3 * HS_FLOATS + D * LDP);   // 3 mbarriers (byte off 165888, 8B aligned)

    int t = threadIdx.x, lane = t & 31, w = t >> 5;
    int wm = w & 3, wn = w >> 2;
    int lm = lane >> 2, lw = lane & 3;
    int e0 = blockIdx.x * 128;
    int wide = g_IDXW;

    if (t == 0) { mbar_init(mbb, 1); mbar_init(mbb + 8, 1); mbar_init(mbb + 16, 1); }

    // stage XJ tile (needed by both passes)
    for (int idx = t; idx < D * 32; idx += 256) {
        int r = idx >> 5, c4 = idx & 31;
        *(float4*)&sXJ[r * LDP + c4 * 4] = *(const float4*)&g_XJ[(size_t)(e0 + r) * D + c4 * 4];
    }
    __syncthreads();

    if (t == 0) {   // prefetch half-slices 0, 1
        mbar_arrive_tx(mbb, HS_BYTES);
        bulk_g2s(s2u(sB), g_W2T, HS_BYTES, mbb);
        mbar_arrive_tx(mbb + 8, HS_BYTES);
        bulk_g2s(s2u(sB) + HS_BYTES, g_W2T + HS_FLOATS, HS_BYTES, mbb + 8);
    }

    // per-n B addressing: o = wn*64 + n*8 + lm
    int boN[8], xrN[8];
#pragma unroll
    for (int n = 0; n < 8; n++) {
        int o = wn * 64 + n * 8 + lm;
        boN[n] = o * 64 + lw;
        xrN[n] = o & 7;
    }

    unsigned a[2][8][4];            // A fragments for current half (rna tf32)
    float fac[2][8][4];             // final accumulator
#pragma unroll
    for (int m = 0; m < 2; m++)
#pragma unroll
        for (int n = 0; n < 8; n++)
#pragma unroll
            for (int q = 0; q < 4; q++) fac[m][n][q] = 0.0f;

#pragma unroll 1
    for (int kk = 0; kk < NSLICE; kk++) {
        if (kk == 0 || kk == 129) {     // (re)load A fragments for this half
            int hb = (kk == 0) ? 0 : 64;
#pragma unroll
            for (int m = 0; m < 2; m++) {
                int r0 = wm * 32 + m * 16 + lm;
#pragma unroll
                for (int ks = 0; ks < 8; ks++) {
                    int c = hb + ks * 8 + lw;
                    a[m][ks][0] = rna_tf32(sXJ[r0 * LDP + c]);
                    a[m][ks][1] = rna_tf32(sXJ[(r0 + 8) * LDP + c]);
                    a[m][ks][2] = rna_tf32(sXJ[r0 * LDP + c + 4]);
                    a[m][ks][3] = rna_tf32(sXJ[(r0 + 8) * LDP + c + 4]);
                }
            }
        }
        if (t == 0 && kk + 2 < NSLICE) {    // prefetch kk+2 (its buffer consumed at kk-1)
            int nb = (kk + 2) % 3;
            mbar_arrive_tx(mbb + nb * 8, HS_BYTES);
            bulk_g2s(s2u(sB) + (uint32_t)nb * HS_BYTES,
                     g_W2T + (size_t)(kk + 2) * HS_FLOATS, HS_BYTES, mbb + nb * 8);
        }

        int k = (kk < 129) ? kk : kk - 129;
        float h0, h1, h2, h3;
        if (k < 128) {
            const float* hp = g_HT + (size_t)k * E + e0 + wm * 32 + lm;
            h0 = hp[0]; h1 = hp[8]; h2 = hp[16]; h3 = hp[24];
        } else { h0 = h1 = h2 = h3 = 1.0f; }    // b2 slice

        mbar_wait(mbb + (kk % 3) * 8, (uint32_t)((kk / 3) & 1));
        const float* B = sB + (kk % 3) * HS_FLOATS;

        float P[2][8][4];
#pragma unroll
        for (int m = 0; m < 2; m++)
#pragma unroll
            for (int n = 0; n < 8; n++)
#pragma unroll
                for (int q = 0; q < 4; q++) P[m][n][q] = 0.0f;

#pragma unroll
        for (int ks = 0; ks < 8; ks++) {
            int g0 = (2 * ks) << 2, g1 = (2 * ks + 1) << 2;   // pre-shift swizzle groups
#pragma unroll
            for (int n = 0; n < 8; n++) {
                unsigned f0 = __float_as_uint(B[boN[n] + (g0 ^ (xrN[n] << 2))]);
                unsigned f1 = __float_as_uint(B[boN[n] + (g1 ^ (xrN[n] << 2))]);
#pragma unroll
                for (int m = 0; m < 2; m++) {
                    asm volatile(
                        "mma.sync.aligned.m16n8k8.row.col.f32.tf32.tf32.f32 "
                        "{%0,%1,%2,%3}, {%4,%5,%6,%7}, {%8,%9}, {%0,%1,%2,%3};"
                        : "+f"(P[m][n][0]), "+f"(P[m][n][1]),
                          "+f"(P[m][n][2]), "+f"(P[m][n][3])
                        : "r"(a[m][ks][0]), "r"(a[m][ks][1]),
                          "r"(a[m][ks][2]), "r"(a[m][ks][3]),
                          "r"(f0), "r"(f1));
                }
            }
        }

        // epilogue: final += h (.) P   (rows: m0 -> lm, lm+8 ; m1 -> lm+16, lm+24)
#pragma unroll
        for (int n = 0; n < 8; n++) {
            fac[0][n][0] = fmaf(h0, P[0][n][0], fac[0][n][0]);
            fac[0][n][1] = fmaf(h0, P[0][n][1], fac[0][n][1]);
            fac[0][n][2] = fmaf(h1, P[0][n][2], fac[0][n][2]);
            fac[0][n][3] = fmaf(h1, P[0][n][3], fac[0][n][3]);
            fac[1][n][0] = fmaf(h2, P[1][n][0], fac[1][n][0]);
            fac[1][n][1] = fmaf(h2, P[1][n][1], fac[1][n][1]);
            fac[1][n][2] = fmaf(h3, P[1][n][2], fac[1][n][2]);
            fac[1][n][3] = fmaf(h3, P[1][n][3], fac[1][n][3]);
        }
        __syncthreads();      // everyone done reading buffer kk%3 -> reissue safe next iter
    }

    // scatter-add into g_SEG
#pragma unroll
    for (int m = 0; m < 2; m++) {
        int rl = wm * 32 + m * 16 + lm;
        int dl = ld_dst(ei, wide, e0 + rl);
        int dh = ld_dst(ei, wide, e0 + rl + 8);
#pragma unroll
        for (int n = 0; n < 8; n++) {
            int c = wn * 64 + n * 8 + lw * 2;
            atomicAdd(&g_SEG[(size_t)dl * D + c],     fac[m][n][0]);
            atomicAdd(&g_SEG[(size_t)dl * D + c + 1], fac[m][n][1]);
            atomicAdd(&g_SEG[(size_t)dh * D + c],     fac[m][n][2]);
            atomicAdd(&g_SEG[(size_t)dh * D + c + 1], fac[m][n][3]);
        }
    }
}

// ---------------- 6. out = x + gelu(seg/cnt + x@root + bias) ----------------
__global__ void __launch_bounds__(256) k_out(const float* __restrict__ x,
                                             const float* __restrict__ root,
                                             const float* __restrict__ bias,
                                             float* __restrict__ out) {
    extern __shared__ float sm[];
    float* sX = sm;
    float* sR = sm + D * LDP;
    int t = threadIdx.x;
    int v0 = blockIdx.x * 128;
    for (int idx = t; idx < D * 32; idx += 256) {
        int r = idx >> 5, c4 = idx & 31;
        float4 z = make_float4(0.f, 0.f, 0.f, 0.f);
        *(float4*)&sX[r * LDP + c4 * 4] =
            (v0 + r < NN) ? *(const float4*)&x[(size_t)(v0 + r) * D + c4 * 4] : z;
        *(float4*)&sR[r * LDP + c4 * 4] = *(const float4*)&root[(size_t)r * D + c4 * 4];
    }
    __syncthreads();
    int tx = t & 15, ty = t >> 4;
    int r0 = ty * 8, c0 = tx * 8;
    float acc[8][8];
#pragma unroll
    for (int u = 0; u < 8; u++)
#pragma unroll
        for (int v = 0; v < 8; v++) acc[u][v] = 0.0f;
    for (int i = 0; i < D; i++) {
        float ar[8];
#pragma unroll
        for (int u = 0; u < 8; u++) ar[u] = sX[(r0 + u) * LDP + i];
        float4 bA = *(float4*)&sR[i * LDP + c0];
        float4 bB = *(float4*)&sR[i * LDP + c0 + 4];
        float br[8] = {bA.x, bA.y, bA.z, bA.w, bB.x, bB.y, bB.z, bB.w};
#pragma unroll
        for (int u = 0; u < 8; u++)
#pragma unroll
            for (int v = 0; v < 8; v++) acc[u][v] = fmaf(ar[u], br[v], acc[u][v]);
    }
#pragma unroll
    for (int u = 0; u < 8; u++) {
        int vtx = v0 + r0 + u;
        if (vtx >= NN) continue;
        float inv = 1.0f / fmaxf(g_CNT[vtx], 1.0f);
#pragma unroll
        for (int v = 0; v < 8; v++) {
            int c = c0 + v;
            float conv = acc[u][v] + g_SEG[(size_t)vtx * D + c] * inv + bias[c];
            float g = 0.5f * conv * (1.0f + erff(conv * 0.70710678118654752f));
            out[(size_t)vtx * D + c] = x[(size_t)vtx * D + c] + g;
        }
    }
}

// ---------------- host ----------------
#define SMEM_GEMM (2 * D * LDP * 4)                        // 135168
#define SMEM_MAIN ((3 * HS_FLOATS + D * LDP) * 4 + 32)     // 165920

extern "C" void kernel_launch(void* const* d_in, const int* in_sizes, int n_in,
                              void* d_out, int out_size) {
    const float* x    = (const float*)d_in[0];
    const void*  ei   = d_in[1];                    // int32 or int64 — detected on device
    const float* ea   = (const float*)d_in[2];
    const float* w1   = (const float*)d_in[3];
    const float* b1   = (const float*)d_in[4];
    const float* w2   = (const float*)d_in[5];
    const float* b2   = (const float*)d_in[6];
    const float* root = (const float*)d_in[7];
    const float* bias = (const float*)d_in[8];
    float* out = (float*)d_out;

    cudaFuncSetAttribute(k_h,    cudaFuncAttributeMaxDynamicSharedMemorySize, SMEM_GEMM);
    cudaFuncSetAttribute(k_out,  cudaFuncAttributeMaxDynamicSharedMemorySize, SMEM_GEMM);
    cudaFuncSetAttribute(k_main, cudaFuncAttributeMaxDynamicSharedMemorySize, SMEM_MAIN);

    k_zero  <<<(NN * D + NN + 255) / 256, 256>>>();
    k_detect<<<E / 256, 256>>>(ei);
    k_w2t   <<<dim3(129, 16), dim3(32, 8)>>>(w2, b2);
    k_h     <<<E / 128, 256, SMEM_GEMM>>>(ea, w1, b1);
    k_gather<<<(E * 32) / 256, 256>>>(x, ei);
    k_cnt   <<<E / 256, 256>>>(ei);
    k_main  <<<E / 128, 256, SMEM_MAIN>>>(ei);
    k_out   <<<(NN + 127) / 128, 256, SMEM_GEMM>>>(x, root, bias, out);
}